// round 7
// baseline (speedup 1.0000x reference)
#include <cuda_runtime.h>
#include <cuda_bf16.h>
#include <cstdint>

#define Bn   32
#define Cn   512
#define HWn  448
#define NHn  8
#define DKn  64
#define NKVn 1024
#define NQn  (HWn * NHn * DKn)   // 229376
#define BHT  (Bn * NHn)          // 256
#define SCALE 0.125f

typedef unsigned long long ull;

// ----------------------------- mma / async helpers -------------------------
__device__ __forceinline__ uint32_t smem_u32(const void* p) {
    uint32_t a;
    asm("{ .reg .u64 t; cvta.to.shared.u64 t, %1; cvt.u32.u64 %0, t; }" : "=r"(a) : "l"(p));
    return a;
}
__device__ __forceinline__ void ldsm4(uint32_t* r, uint32_t addr) {
    asm volatile("ldmatrix.sync.aligned.m8n8.x4.shared.b16 {%0,%1,%2,%3}, [%4];"
        : "=r"(r[0]), "=r"(r[1]), "=r"(r[2]), "=r"(r[3]) : "r"(addr));
}
__device__ __forceinline__ void ldsm4t(uint32_t* r, uint32_t addr) {
    asm volatile("ldmatrix.sync.aligned.m8n8.x4.trans.shared.b16 {%0,%1,%2,%3}, [%4];"
        : "=r"(r[0]), "=r"(r[1]), "=r"(r[2]), "=r"(r[3]) : "r"(addr));
}
__device__ __forceinline__ void mma_bf16(float* c, const uint32_t* a, uint32_t b0, uint32_t b1) {
    asm volatile("mma.sync.aligned.m16n8k16.row.col.f32.bf16.bf16.f32 "
        "{%0,%1,%2,%3}, {%4,%5,%6,%7}, {%8,%9}, {%0,%1,%2,%3};"
        : "+f"(c[0]), "+f"(c[1]), "+f"(c[2]), "+f"(c[3])
        : "r"(a[0]), "r"(a[1]), "r"(a[2]), "r"(a[3]), "r"(b0), "r"(b1));
}
__device__ __forceinline__ void mma_tf32(float* c, const float* a, float b0, float b1) {
    asm volatile("mma.sync.aligned.m16n8k8.row.col.f32.tf32.tf32.f32 "
        "{%0,%1,%2,%3}, {%4,%5,%6,%7}, {%8,%9}, {%0,%1,%2,%3};"
        : "+f"(c[0]), "+f"(c[1]), "+f"(c[2]), "+f"(c[3])
        : "r"(__float_as_uint(a[0])), "r"(__float_as_uint(a[1])),
          "r"(__float_as_uint(a[2])), "r"(__float_as_uint(a[3])),
          "r"(__float_as_uint(b0)), "r"(__float_as_uint(b1)));
}
__device__ __forceinline__ uint32_t bf2(float a, float b) {
    __nv_bfloat162 p = __float22bfloat162_rn(make_float2(a, b));
    return *(uint32_t*)&p;
}
__device__ __forceinline__ void cpa16(uint32_t dst, const void* src) {
    asm volatile("cp.async.cg.shared.global [%0], [%1], 16;" :: "r"(dst), "l"(src));
}
#define CP_COMMIT() asm volatile("cp.async.commit_group;" ::: "memory")
#define CP_WAIT2()  asm volatile("cp.async.wait_group 2;" ::: "memory")
#define CP_WAIT1()  asm volatile("cp.async.wait_group 1;" ::: "memory")
#define CP_WAIT0()  asm volatile("cp.async.wait_group 0;" ::: "memory")

// --------------------------- scratch globals -------------------------------
__device__ __nv_bfloat16 g_xt  [(size_t)Bn * HWn * Cn];    // [b][j][c]
__device__ __nv_bfloat16 g_Wt  [(size_t)NKVn * Cn];        // [n][c]
__device__ __nv_bfloat16 g_WoT [(size_t)Cn * Cn];          // [c][n]
__device__ __nv_bfloat16 g_qb  [(size_t)BHT * HWn * DKn];  // [bh][i][d]
__device__ __nv_bfloat16 g_kb  [(size_t)BHT * HWn * DKn];  // [bh][j][d]
__device__ float         g_v   [(size_t)BHT * HWn * DKn];  // [bh][j][d]
__device__ __nv_bfloat16 g_Eb  [(size_t)BHT * HWn * HWn];  // [bh][i][j]
__device__ float         g_cs  [BHT * HWn];
__device__ __nv_bfloat16 g_vt  [(size_t)BHT * DKn * HWn];  // [bh][d][j] (v/cs)
__device__ __nv_bfloat16 g_resb[(size_t)Bn * HWn * Cn];    // [b][i][h*64+d] bf16

// ===================== prep: x -> xt[b][j][c] bf16 ==========================
__global__ __launch_bounds__(256) void k_prep_x(const float* __restrict__ x) {
    __shared__ float t[64][65];
    int b = blockIdx.z, j0 = blockIdx.y * 64, c0 = blockIdx.x * 64;
    int tid = threadIdx.x;
    for (int u = tid; u < 4096; u += 256) {
        int cc = u >> 6, jj = u & 63;
        t[cc][jj] = x[((size_t)b * Cn + c0 + cc) * HWn + j0 + jj];
    }
    __syncthreads();
    for (int u = tid; u < 4096; u += 256) {
        int jj = u >> 6, cc = u & 63;
        g_xt[((size_t)b * HWn + j0 + jj) * Cn + c0 + cc] = __float2bfloat16(t[cc][jj]);
    }
}

// ===================== prep: W_kv -> Wt[n][c] bf16 ==========================
__global__ __launch_bounds__(256) void k_prep_w(const float* __restrict__ Wkv) {
    __shared__ float t[64][65];
    int n0 = blockIdx.y * 64, c0 = blockIdx.x * 64;
    int tid = threadIdx.x;
    for (int u = tid; u < 4096; u += 256) {
        int cc = u >> 6, nn = u & 63;
        t[cc][nn] = Wkv[(size_t)(c0 + cc) * NKVn + n0 + nn];
    }
    __syncthreads();
    for (int u = tid; u < 4096; u += 256) {
        int nn = u >> 6, cc = u & 63;
        g_Wt[(size_t)(n0 + nn) * Cn + c0 + cc] = __float2bfloat16(t[cc][nn]);
    }
}

// ===================== prep: W_o -> WoT[c][n] bf16 ==========================
__global__ __launch_bounds__(256) void k_prep_wo(const float* __restrict__ Wo) {
    __shared__ float t[64][65];
    int c0 = blockIdx.y * 64, n0 = blockIdx.x * 64;
    int tid = threadIdx.x;
    for (int u = tid; u < 4096; u += 256) {
        int nn = u >> 6, cc = u & 63;
        t[nn][cc] = Wo[(size_t)(n0 + nn) * Cn + c0 + cc];
    }
    __syncthreads();
    for (int u = tid; u < 4096; u += 256) {
        int cc = u >> 6, nn = u & 63;
        g_WoT[(size_t)(c0 + cc) * Cn + n0 + nn] = __float2bfloat16(t[nn][cc]);
    }
}

// ============ KV projection (mma, cp.async 2-stage): head per CTA ==========
__global__ __launch_bounds__(256) void k_kv_m(const float* __restrict__ bkv) {
    extern __shared__ char sm[];
    int h = blockIdx.x, j0 = blockIdx.y * 128, b = blockIdx.z;
    int bh = b * NHn + h;
    int tid = threadIdx.x, lane = tid & 31, wid = tid >> 5;
    int wm = wid >> 1, wn = wid & 1;
    uint32_t base = smem_u32(sm);
    float acc[2][8][4] = {};
    auto issue = [&](int st, int c0) {
        uint32_t ab = base + st * 32768, bb = ab + 16384;
        for (int u = tid; u < 1024; u += 256) {
            int r = u >> 3, cb = u & 7;
            int j = min(j0 + r, HWn - 1);
            cpa16(ab + r * 128 + ((cb ^ (r & 7)) << 4),
                  g_xt + ((size_t)b * HWn + j) * Cn + c0 + cb * 8);
            cpa16(bb + r * 128 + ((cb ^ (r & 7)) << 4),
                  g_Wt + (size_t)(h * 128 + r) * Cn + c0 + cb * 8);
        }
        CP_COMMIT();
    };
    issue(0, 0);
    for (int s = 0; s < 8; s++) {
        int st = s & 1;
        if (s < 7) { issue(st ^ 1, (s + 1) * 64); CP_WAIT1(); } else { CP_WAIT0(); }
        __syncthreads();
        uint32_t aBase = base + st * 32768, bBase = aBase + 16384;
        #pragma unroll
        for (int kk = 0; kk < 4; kk++) {
            uint32_t af[2][4], bf[4][4];
            int cb = kk * 2 + (lane >> 4);
            #pragma unroll
            for (int mi = 0; mi < 2; mi++) {
                int row = wm * 32 + mi * 16 + (lane & 15);
                ldsm4(af[mi], aBase + row * 128 + ((cb ^ (row & 7)) << 4));
            }
            #pragma unroll
            for (int np = 0; np < 4; np++) {
                int row = wn * 64 + np * 16 + (lane & 15);
                ldsm4(bf[np], bBase + row * 128 + ((cb ^ (row & 7)) << 4));
            }
            #pragma unroll
            for (int mi = 0; mi < 2; mi++)
                #pragma unroll
                for (int ni = 0; ni < 8; ni++)
                    mma_bf16(acc[mi][ni], af[mi], bf[ni >> 1][ni & 1], bf[ni >> 1][2 + (ni & 1)]);
        }
        __syncthreads();
    }
    #pragma unroll
    for (int mi = 0; mi < 2; mi++) {
        int m0 = wm * 32 + mi * 16 + (lane >> 2);
        #pragma unroll
        for (int ni = 0; ni < 8; ni++) {
            int n = wn * 64 + ni * 8 + (lane & 3) * 2;
            float b0v = bkv[h * 128 + n], b1v = bkv[h * 128 + n + 1];
            #pragma unroll
            for (int rr = 0; rr < 2; rr++) {
                int j = j0 + m0 + rr * 8;
                if (j < HWn) {
                    float v0 = acc[mi][ni][rr * 2] + b0v;
                    float v1 = acc[mi][ni][rr * 2 + 1] + b1v;
                    if (n < 64) {
                        *(uint32_t*)(g_kb + ((size_t)bh * HWn + j) * DKn + n) = bf2(v0, v1);
                    } else {
                        *(float2*)(g_v + ((size_t)bh * HWn + j) * DKn + n - 64) = make_float2(v0, v1);
                    }
                }
            }
        }
    }
}

// ========= Q projection (tf32 mma, cp.async fp32 3-stage pipeline) =========
// Per CTA: N_TILE=256 output columns, M=32, K=512 in 32 slabs of 16.
// smem: Ss fp32 [32][512] swizzled (64KB) + 3 stages of fp32 W_q slab
//       [16][256] (16KB each). Total 112KB dynamic.
__global__ __launch_bounds__(256) void k_q_m(const float* __restrict__ s,
                                             const float* __restrict__ Wq,
                                             const float* __restrict__ bq) {
    extern __shared__ char sm[];
    const int STG0 = 65536;
    uint32_t base = smem_u32(sm);
    int n0 = blockIdx.x * 256;
    int tid = threadIdx.x, lane = tid & 31, wid = tid >> 5;
    // load s into Ss fp32 swizzled: addr = m*2048 + ((g ^ (m&7))<<4), g = c>>2
    for (int u = tid; u < 4096; u += 256) {
        int m = u >> 7, g = u & 127;
        float4 v = *(const float4*)(s + (size_t)m * Cn + g * 4);
        *(float4*)(sm + m * 2048 + ((g ^ (m & 7)) << 4)) = v;
    }
    auto issue = [&](int slab) {
        uint32_t st = base + STG0 + (slab % 3) * 16384;
        const float* src = Wq + (size_t)(slab * 16) * NQn + n0;
        for (int u = tid; u < 1024; u += 256) {
            int row = u >> 6, g = u & 63;
            cpa16(st + row * 1024 + ((g ^ (row & 7)) << 4),
                  src + (size_t)row * NQn + g * 4);
        }
        CP_COMMIT();
    };
    issue(0); issue(1); issue(2);
    float acc[2][4][4] = {};
    int mrow = lane >> 2, kq = lane & 3;   // fragment coords
    for (int slab = 0; slab < 32; slab++) {
        if (slab < 30) CP_WAIT2(); else if (slab == 30) CP_WAIT1(); else CP_WAIT0();
        __syncthreads();
        char* st = sm + STG0 + (slab % 3) * 16384;
        #pragma unroll
        for (int ks = 0; ks < 2; ks++) {
            int kb = slab * 16 + ks * 8;        // global k of this k8 step
            float af[2][4];
            #pragma unroll
            for (int mi = 0; mi < 2; mi++) {
                int m0 = mi * 16 + mrow;
                int k0g = (kb + kq) >> 2, k0o = (kb + kq) & 3;
                int k1g = (kb + 4 + kq) >> 2, k1o = (kb + 4 + kq) & 3;
                af[mi][0] = *(float*)(sm + m0 * 2048 + ((k0g ^ (m0 & 7)) << 4) + k0o * 4);
                af[mi][1] = *(float*)(sm + (m0 + 8) * 2048 + ((k0g ^ ((m0 + 8) & 7)) << 4) + k0o * 4);
                af[mi][2] = *(float*)(sm + m0 * 2048 + ((k1g ^ (m0 & 7)) << 4) + k1o * 4);
                af[mi][3] = *(float*)(sm + (m0 + 8) * 2048 + ((k1g ^ ((m0 + 8) & 7)) << 4) + k1o * 4);
            }
            int r0 = ks * 8 + kq, r1 = ks * 8 + 4 + kq;   // rows within slab
            #pragma unroll
            for (int ni = 0; ni < 4; ni++) {
                int n = wid * 32 + ni * 8 + mrow;          // 0..255
                int g = n >> 2, no = n & 3;
                float b0 = *(float*)(st + r0 * 1024 + ((g ^ (r0 & 7)) << 4) + no * 4);
                float b1 = *(float*)(st + r1 * 1024 + ((g ^ (r1 & 7)) << 4) + no * 4);
                mma_tf32(acc[0][ni], af[0], b0, b1);
                mma_tf32(acc[1][ni], af[1], b0, b1);
            }
        }
        __syncthreads();
        if (slab < 29) issue(slab + 3);
    }
    #pragma unroll
    for (int mi = 0; mi < 2; mi++) {
        int m0 = mi * 16 + mrow;
        #pragma unroll
        for (int ni = 0; ni < 4; ni++) {
            int n = n0 + wid * 32 + ni * 8 + kq * 2;
            int i = n >> 9, h = (n >> 6) & 7, d = n & 63;
            float b0v = bq[n], b1v = bq[n + 1];
            #pragma unroll
            for (int rr = 0; rr < 2; rr++) {
                int bidx = m0 + rr * 8;
                *(uint32_t*)(g_qb + (((size_t)bidx * NHn + h) * HWn + i) * DKn + d) =
                    bf2(acc[mi][ni][rr * 2] + b0v, acc[mi][ni][rr * 2 + 1] + b1v);
            }
        }
    }
}

// ================= zero colsum =============================================
__global__ void k_zero() {
    int i = blockIdx.x * blockDim.x + threadIdx.x;
    if (i < BHT * HWn) g_cs[i] = 0.0f;
}

// ======== E = exp(scale*QK^T) (mma) + column sums ==========================
__global__ __launch_bounds__(256) void k_attE_m() {
    __shared__ __nv_bfloat16 Qs[128 * 64];
    __shared__ __nv_bfloat16 Ks[128 * 64];
    int j0 = blockIdx.x * 112, i0 = blockIdx.y * 128, bh = blockIdx.z;
    int tid = threadIdx.x, lane = tid & 31, wid = tid >> 5;
    int wm = wid >> 1, wn = wid & 1;
    uint32_t qBase = smem_u32(Qs), kBase = smem_u32(Ks);
    for (int u = tid; u < 2048; u += 256) {
        int half = u >> 10, w = u & 1023, r = w >> 3, cb = w & 7;
        if (half == 0) {
            int i = min(i0 + r, HWn - 1);
            *(uint4*)((char*)Qs + r * 128 + ((cb ^ (r & 7)) << 4)) =
                *(const uint4*)(g_qb + ((size_t)bh * HWn + i) * DKn + cb * 8);
        } else {
            int j = min(j0 + r, HWn - 1);
            *(uint4*)((char*)Ks + r * 128 + ((cb ^ (r & 7)) << 4)) =
                *(const uint4*)(g_kb + ((size_t)bh * HWn + j) * DKn + cb * 8);
        }
    }
    __syncthreads();
    float acc[2][7][4] = {};
    #pragma unroll
    for (int kk = 0; kk < 4; kk++) {
        uint32_t af[2][4], bf[4][4];
        int cb = kk * 2 + (lane >> 4);
        #pragma unroll
        for (int mi = 0; mi < 2; mi++) {
            int row = wm * 32 + mi * 16 + (lane & 15);
            ldsm4(af[mi], qBase + row * 128 + ((cb ^ (row & 7)) << 4));
        }
        #pragma unroll
        for (int np = 0; np < 4; np++) {
            int row = wn * 56 + np * 16 + (lane & 15);
            ldsm4(bf[np], kBase + row * 128 + ((cb ^ (row & 7)) << 4));
        }
        #pragma unroll
        for (int mi = 0; mi < 2; mi++)
            #pragma unroll
            for (int ni = 0; ni < 7; ni++)
                mma_bf16(acc[mi][ni], af[mi], bf[ni >> 1][ni & 1], bf[ni >> 1][2 + (ni & 1)]);
    }
    #pragma unroll
    for (int ni = 0; ni < 7; ni++) {
        int n = j0 + wn * 56 + ni * 8 + (lane & 3) * 2;
        float cs0 = 0.f, cs1 = 0.f;
        #pragma unroll
        for (int mi = 0; mi < 2; mi++) {
            int ib = i0 + wm * 32 + mi * 16 + (lane >> 2);
            #pragma unroll
            for (int rr = 0; rr < 2; rr++) {
                int i = ib + rr * 8;
                float e0 = 0.f, e1 = 0.f;
                if (i < HWn) {
                    e0 = __expf(acc[mi][ni][rr * 2] * SCALE);
                    e1 = __expf(acc[mi][ni][rr * 2 + 1] * SCALE);
                    *(uint32_t*)(g_Eb + ((size_t)bh * HWn + i) * HWn + n) = bf2(e0, e1);
                }
                cs0 += e0; cs1 += e1;
            }
        }
        #pragma unroll
        for (int o = 4; o <= 16; o <<= 1) {
            cs0 += __shfl_xor_sync(0xffffffffu, cs0, o);
            cs1 += __shfl_xor_sync(0xffffffffu, cs1, o);
        }
        if ((lane >> 2) == 0) {
            atomicAdd(&g_cs[bh * HWn + n], cs0);
            atomicAdd(&g_cs[bh * HWn + n + 1], cs1);
        }
    }
}

// ========== v' = v/colsum, transposed [bh][d][j] bf16 ======================
__global__ __launch_bounds__(256) void k_vnorm_t() {
    __shared__ float t[64][65];
    int j0 = blockIdx.x * 64, bh = blockIdx.y;
    int tid = threadIdx.x;
    for (int u = tid; u < 4096; u += 256) {
        int jj = u >> 6, dd = u & 63;
        t[jj][dd] = g_v[((size_t)bh * HWn + j0 + jj) * DKn + dd] / g_cs[bh * HWn + j0 + jj];
    }
    __syncthreads();
    for (int u = tid; u < 4096; u += 256) {
        int dd = u >> 6, jj = u & 63;
        g_vt[((size_t)bh * DKn + dd) * HWn + j0 + jj] = __float2bfloat16(t[jj][dd]);
    }
}

// ========== AV (mma, cp.async 2-stage): res[i][d] = sum_j E * v' ===========
__global__ __launch_bounds__(256) void k_av_m() {
    extern __shared__ char sm[];
    int i0 = blockIdx.x * 128, bh = blockIdx.y;
    int b = bh >> 3, h = bh & 7;
    int tid = threadIdx.x, lane = tid & 31, wid = tid >> 5;
    int wm = wid >> 1, wn = wid & 1;
    uint32_t base = smem_u32(sm);
    float acc[2][4][4] = {};
    auto issue = [&](int st, int jc) {
        uint32_t eb = base + st * 24576, vb = eb + 16384;
        for (int u = tid; u < 1536; u += 256) {
            if (u < 1024) {
                int r = u >> 3, cb = u & 7;
                int i = min(i0 + r, HWn - 1);
                cpa16(eb + r * 128 + ((cb ^ (r & 7)) << 4),
                      g_Eb + ((size_t)bh * HWn + i) * HWn + jc + cb * 8);
            } else {
                int w = u - 1024, r = w >> 3, cb = w & 7;
                cpa16(vb + r * 128 + ((cb ^ (r & 7)) << 4),
                      g_vt + ((size_t)bh * DKn + r) * HWn + jc + cb * 8);
            }
        }
        CP_COMMIT();
    };
    issue(0, 0);
    for (int s = 0; s < 7; s++) {
        int st = s & 1;
        if (s < 6) { issue(st ^ 1, (s + 1) * 64); CP_WAIT1(); } else { CP_WAIT0(); }
        __syncthreads();
        uint32_t eBase = base + st * 24576, vBase = eBase + 16384;
        #pragma unroll
        for (int kk = 0; kk < 4; kk++) {
            uint32_t af[2][4], bf[2][4];
            int cb = kk * 2 + (lane >> 4);
            #pragma unroll
            for (int mi = 0; mi < 2; mi++) {
                int row = wm * 32 + mi * 16 + (lane & 15);
                ldsm4(af[mi], eBase + row * 128 + ((cb ^ (row & 7)) << 4));
            }
            #pragma unroll
            for (int np = 0; np < 2; np++) {
                int row = wn * 32 + np * 16 + (lane & 15);
                ldsm4(bf[np], vBase + row * 128 + ((cb ^ (row & 7)) << 4));
            }
            #pragma unroll
            for (int mi = 0; mi < 2; mi++)
                #pragma unroll
                for (int ni = 0; ni < 4; ni++)
                    mma_bf16(acc[mi][ni], af[mi], bf[ni >> 1][ni & 1], bf[ni >> 1][2 + (ni & 1)]);
        }
        __syncthreads();
    }
    #pragma unroll
    for (int mi = 0; mi < 2; mi++) {
        int ib = i0 + wm * 32 + mi * 16 + (lane >> 2);
        #pragma unroll
        for (int ni = 0; ni < 4; ni++) {
            int d = wn * 32 + ni * 8 + (lane & 3) * 2;
            #pragma unroll
            for (int rr = 0; rr < 2; rr++) {
                int i = ib + rr * 8;
                if (i < HWn)
                    *(uint32_t*)(g_resb + ((size_t)b * HWn + i) * Cn + h * 64 + d) =
                        bf2(acc[mi][ni][rr * 2], acc[mi][ni][rr * 2 + 1]);
            }
        }
    }
}

// ====== O projection (mma bf16, cp.async 2-stage) + bias + residual ========
__global__ __launch_bounds__(256) void k_out_m(const float* __restrict__ x,
                                               const float* __restrict__ bo,
                                               float* __restrict__ out) {
    extern __shared__ char sm[];
    int b = blockIdx.z, c0 = blockIdx.y * 128, j0 = blockIdx.x * 128;
    int tid = threadIdx.x, lane = tid & 31, wid = tid >> 5;
    int wm = wid >> 1, wn = wid & 1;
    uint32_t base = smem_u32(sm);
    float acc[2][8][4] = {};
    auto issue = [&](int st, int n0) {
        uint32_t ab = base + st * 32768, bb = ab + 16384;
        for (int u = tid; u < 1024; u += 256) {
            int r = u >> 3, cb = u & 7;
            cpa16(ab + r * 128 + ((cb ^ (r & 7)) << 4),
                  g_WoT + (size_t)(c0 + r) * Cn + n0 + cb * 8);
            int j = min(j0 + r, HWn - 1);
            cpa16(bb + r * 128 + ((cb ^ (r & 7)) << 4),
                  g_resb + ((size_t)b * HWn + j) * Cn + n0 + cb * 8);
        }
        CP_COMMIT();
    };
    issue(0, 0);
    for (int s = 0; s < 8; s++) {
        int st = s & 1;
        if (s < 7) { issue(st ^ 1, (s + 1) * 64); CP_WAIT1(); } else { CP_WAIT0(); }
        __syncthreads();
        uint32_t aBase = base + st * 32768, bBase = aBase + 16384;
        #pragma unroll
        for (int kk = 0; kk < 4; kk++) {
            uint32_t af[2][4], bf[4][4];
            int cb = kk * 2 + (lane >> 4);
            #pragma unroll
            for (int mi = 0; mi < 2; mi++) {
                int row = wm * 32 + mi * 16 + (lane & 15);
                ldsm4(af[mi], aBase + row * 128 + ((cb ^ (row & 7)) << 4));
            }
            #pragma unroll
            for (int np = 0; np < 4; np++) {
                int row = wn * 64 + np * 16 + (lane & 15);
                ldsm4(bf[np], bBase + row * 128 + ((cb ^ (row & 7)) << 4));
            }
            #pragma unroll
            for (int mi = 0; mi < 2; mi++)
                #pragma unroll
                for (int ni = 0; ni < 8; ni++)
                    mma_bf16(acc[mi][ni], af[mi], bf[ni >> 1][ni & 1], bf[ni >> 1][2 + (ni & 1)]);
        }
        __syncthreads();
    }
    // epilogue: stage fp32 tile [128 c][64 j] per half, then coalesced out
    float* stg = (float*)sm;
    #pragma unroll
    for (int half = 0; half < 2; half++) {
        if (wn == half) {
            #pragma unroll
            for (int mi = 0; mi < 2; mi++) {
                #pragma unroll
                for (int ni = 0; ni < 8; ni++) {
                    int jj = ni * 8 + (lane & 3) * 2;
                    #pragma unroll
                    for (int rr = 0; rr < 2; rr++) {
                        int c = wm * 32 + mi * 16 + (lane >> 2) + rr * 8;
                        stg[c * 66 + jj]     = acc[mi][ni][rr * 2];
                        stg[c * 66 + jj + 1] = acc[mi][ni][rr * 2 + 1];
                    }
                }
            }
        }
        __syncthreads();
        for (int u = tid; u < 4096; u += 256) {
            int c = u >> 5, jj = (u & 31) * 2;
            int j = j0 + half * 64 + jj;
            if (j < HWn) {
                size_t o = ((size_t)b * Cn + c0 + c) * HWn + j;
                float bias = bo[c0 + c];
                float2 xv = *(const float2*)(x + o);
                float2 r = make_float2(stg[c * 66 + jj] + bias + xv.x,
                                       stg[c * 66 + jj + 1] + bias + xv.y);
                *(float2*)(out + o) = r;
            }
        }
        __syncthreads();
    }
}

// ================= launch ==================================================
extern "C" void kernel_launch(void* const* d_in, const int* in_sizes, int n_in,
                              void* d_out, int out_size) {
    const float *x = 0, *s = 0, *Wkv = 0, *bkv = 0, *Wq = 0, *bq = 0, *Wo = 0, *bo = 0;
    for (int i = 0; i < n_in; i++) {
        const float* p = (const float*)d_in[i];
        switch (in_sizes[i]) {
            case 32 * 512 * 448: x = p; break;
            case 32 * 512:       s = p; break;
            case 512 * 1024:     Wkv = p; break;
            case 1024:           bkv = p; break;
            case 512 * 229376:   Wq = p; break;
            case 229376:         bq = p; break;
            case 512 * 512:      Wo = p; break;
            case 512:            bo = p; break;
        }
    }
    float* out = (float*)d_out;

    static int init = 0;
    if (!init) {
        cudaFuncSetAttribute(k_kv_m,  cudaFuncAttributeMaxDynamicSharedMemorySize, 65536);
        cudaFuncSetAttribute(k_q_m,   cudaFuncAttributeMaxDynamicSharedMemorySize, 114688);
        cudaFuncSetAttribute(k_av_m,  cudaFuncAttributeMaxDynamicSharedMemorySize, 49152);
        cudaFuncSetAttribute(k_out_m, cudaFuncAttributeMaxDynamicSharedMemorySize, 65536);
        init = 1;
    }

    k_prep_x <<<dim3(8, 7, Bn), 256>>>(x);
    k_prep_w <<<dim3(8, 16), 256>>>(Wkv);
    k_prep_wo<<<dim3(8, 8), 256>>>(Wo);
    k_q_m    <<<NQn / 256, 256, 114688>>>(s, Wq, bq);
    k_kv_m   <<<dim3(NHn, 4, Bn), 256, 65536>>>(bkv);
    k_zero   <<<(BHT * HWn + 255) / 256, 256>>>();
    k_attE_m <<<dim3(4, 4, BHT), 256>>>();
    k_vnorm_t<<<dim3(7, BHT), 256>>>();
    k_av_m   <<<dim3(4, BHT), 256, 49152>>>();
    k_out_m  <<<dim3(4, 4, Bn), 256, 65536>>>(x, bo, out);
}

// round 9
// speedup vs baseline: 1.0413x; 1.0413x over previous
#include <cuda_runtime.h>
#include <cuda_bf16.h>
#include <cstdint>

#define Bn   32
#define Cn   512
#define HWn  448
#define NHn  8
#define DKn  64
#define NKVn 1024
#define NQn  (HWn * NHn * DKn)   // 229376
#define BHT  (Bn * NHn)          // 256
#define SCALE 0.125f

typedef unsigned long long ull;

// ----------------------------- mma / async helpers -------------------------
__device__ __forceinline__ uint32_t smem_u32(const void* p) {
    uint32_t a;
    asm("{ .reg .u64 t; cvta.to.shared.u64 t, %1; cvt.u32.u64 %0, t; }" : "=r"(a) : "l"(p));
    return a;
}
__device__ __forceinline__ void ldsm4(uint32_t* r, uint32_t addr) {
    asm volatile("ldmatrix.sync.aligned.m8n8.x4.shared.b16 {%0,%1,%2,%3}, [%4];"
        : "=r"(r[0]), "=r"(r[1]), "=r"(r[2]), "=r"(r[3]) : "r"(addr));
}
__device__ __forceinline__ void mma_bf16(float* c, const uint32_t* a, uint32_t b0, uint32_t b1) {
    asm volatile("mma.sync.aligned.m16n8k16.row.col.f32.bf16.bf16.f32 "
        "{%0,%1,%2,%3}, {%4,%5,%6,%7}, {%8,%9}, {%0,%1,%2,%3};"
        : "+f"(c[0]), "+f"(c[1]), "+f"(c[2]), "+f"(c[3])
        : "r"(a[0]), "r"(a[1]), "r"(a[2]), "r"(a[3]), "r"(b0), "r"(b1));
}
__device__ __forceinline__ void mma_tf32(float* c, const float* a, float b0, float b1) {
    asm volatile("mma.sync.aligned.m16n8k8.row.col.f32.tf32.tf32.f32 "
        "{%0,%1,%2,%3}, {%4,%5,%6,%7}, {%8,%9}, {%0,%1,%2,%3};"
        : "+f"(c[0]), "+f"(c[1]), "+f"(c[2]), "+f"(c[3])
        : "r"(__float_as_uint(a[0])), "r"(__float_as_uint(a[1])),
          "r"(__float_as_uint(a[2])), "r"(__float_as_uint(a[3])),
          "r"(__float_as_uint(b0)), "r"(__float_as_uint(b1)));
}
__device__ __forceinline__ uint32_t bf2(float a, float b) {
    __nv_bfloat162 p = __float22bfloat162_rn(make_float2(a, b));
    return *(uint32_t*)&p;
}
__device__ __forceinline__ void cpa16(uint32_t dst, const void* src) {
    asm volatile("cp.async.cg.shared.global [%0], [%1], 16;" :: "r"(dst), "l"(src));
}
#define CP_COMMIT() asm volatile("cp.async.commit_group;" ::: "memory")
#define CP_WAIT3()  asm volatile("cp.async.wait_group 3;" ::: "memory")
#define CP_WAIT2()  asm volatile("cp.async.wait_group 2;" ::: "memory")
#define CP_WAIT1()  asm volatile("cp.async.wait_group 1;" ::: "memory")
#define CP_WAIT0()  asm volatile("cp.async.wait_group 0;" ::: "memory")

// --------------------------- scratch globals -------------------------------
__device__ __nv_bfloat16 g_xt  [(size_t)Bn * HWn * Cn];    // [b][j][c]
__device__ __nv_bfloat16 g_Wt  [(size_t)NKVn * Cn];        // [n][c]
__device__ __nv_bfloat16 g_WoT [(size_t)Cn * Cn];          // [c][n]
__device__ __nv_bfloat16 g_qb  [(size_t)BHT * HWn * DKn];  // [bh][i][d]
__device__ __nv_bfloat16 g_kb  [(size_t)BHT * HWn * DKn];  // [bh][j][d]
__device__ float         g_v   [(size_t)BHT * HWn * DKn];  // [bh][j][d]
__device__ __nv_bfloat16 g_Eb  [(size_t)BHT * HWn * HWn];  // [bh][i][j]
__device__ float         g_cs  [BHT * HWn];
__device__ __nv_bfloat16 g_vt  [(size_t)BHT * DKn * HWn];  // [bh][d][j] (v/cs)
__device__ __nv_bfloat16 g_resb[(size_t)Bn * HWn * Cn];    // [b][i][h*64+d] bf16

// ===================== prep: x -> xt[b][j][c] bf16 ==========================
__global__ __launch_bounds__(256) void k_prep_x(const float* __restrict__ x) {
    __shared__ float t[64][65];
    int b = blockIdx.z, j0 = blockIdx.y * 64, c0 = blockIdx.x * 64;
    int tid = threadIdx.x;
    for (int u = tid; u < 4096; u += 256) {
        int cc = u >> 6, jj = u & 63;
        t[cc][jj] = x[((size_t)b * Cn + c0 + cc) * HWn + j0 + jj];
    }
    __syncthreads();
    for (int u = tid; u < 4096; u += 256) {
        int jj = u >> 6, cc = u & 63;
        g_xt[((size_t)b * HWn + j0 + jj) * Cn + c0 + cc] = __float2bfloat16(t[cc][jj]);
    }
}

// ===================== prep: W_kv -> Wt[n][c] bf16 ==========================
__global__ __launch_bounds__(256) void k_prep_w(const float* __restrict__ Wkv) {
    __shared__ float t[64][65];
    int n0 = blockIdx.y * 64, c0 = blockIdx.x * 64;
    int tid = threadIdx.x;
    for (int u = tid; u < 4096; u += 256) {
        int cc = u >> 6, nn = u & 63;
        t[cc][nn] = Wkv[(size_t)(c0 + cc) * NKVn + n0 + nn];
    }
    __syncthreads();
    for (int u = tid; u < 4096; u += 256) {
        int nn = u >> 6, cc = u & 63;
        g_Wt[(size_t)(n0 + nn) * Cn + c0 + cc] = __float2bfloat16(t[cc][nn]);
    }
}

// ===================== prep: W_o -> WoT[c][n] bf16 ==========================
__global__ __launch_bounds__(256) void k_prep_wo(const float* __restrict__ Wo) {
    __shared__ float t[64][65];
    int c0 = blockIdx.y * 64, n0 = blockIdx.x * 64;
    int tid = threadIdx.x;
    for (int u = tid; u < 4096; u += 256) {
        int nn = u >> 6, cc = u & 63;
        t[nn][cc] = Wo[(size_t)(n0 + nn) * Cn + c0 + cc];
    }
    __syncthreads();
    for (int u = tid; u < 4096; u += 256) {
        int cc = u >> 6, nn = u & 63;
        g_WoT[(size_t)(c0 + cc) * Cn + n0 + nn] = __float2bfloat16(t[nn][cc]);
    }
}

// ============ KV projection (mma, cp.async 2-stage): head per CTA ==========
__global__ __launch_bounds__(256) void k_kv_m(const float* __restrict__ bkv) {
    extern __shared__ char sm[];
    int h = blockIdx.x, j0 = blockIdx.y * 128, b = blockIdx.z;
    int bh = b * NHn + h;
    int tid = threadIdx.x, lane = tid & 31, wid = tid >> 5;
    int wm = wid >> 1, wn = wid & 1;
    uint32_t base = smem_u32(sm);
    float acc[2][8][4] = {};
    auto issue = [&](int st, int c0) {
        uint32_t ab = base + st * 32768, bb = ab + 16384;
        for (int u = tid; u < 1024; u += 256) {
            int r = u >> 3, cb = u & 7;
            int j = min(j0 + r, HWn - 1);
            cpa16(ab + r * 128 + ((cb ^ (r & 7)) << 4),
                  g_xt + ((size_t)b * HWn + j) * Cn + c0 + cb * 8);
            cpa16(bb + r * 128 + ((cb ^ (r & 7)) << 4),
                  g_Wt + (size_t)(h * 128 + r) * Cn + c0 + cb * 8);
        }
        CP_COMMIT();
    };
    issue(0, 0);
    for (int s = 0; s < 8; s++) {
        int st = s & 1;
        if (s < 7) { issue(st ^ 1, (s + 1) * 64); CP_WAIT1(); } else { CP_WAIT0(); }
        __syncthreads();
        uint32_t aBase = base + st * 32768, bBase = aBase + 16384;
        #pragma unroll
        for (int kk = 0; kk < 4; kk++) {
            uint32_t af[2][4], bf[4][4];
            int cb = kk * 2 + (lane >> 4);
            #pragma unroll
            for (int mi = 0; mi < 2; mi++) {
                int row = wm * 32 + mi * 16 + (lane & 15);
                ldsm4(af[mi], aBase + row * 128 + ((cb ^ (row & 7)) << 4));
            }
            #pragma unroll
            for (int np = 0; np < 4; np++) {
                int row = wn * 64 + np * 16 + (lane & 15);
                ldsm4(bf[np], bBase + row * 128 + ((cb ^ (row & 7)) << 4));
            }
            #pragma unroll
            for (int mi = 0; mi < 2; mi++)
                #pragma unroll
                for (int ni = 0; ni < 8; ni++)
                    mma_bf16(acc[mi][ni], af[mi], bf[ni >> 1][ni & 1], bf[ni >> 1][2 + (ni & 1)]);
        }
        __syncthreads();
    }
    #pragma unroll
    for (int mi = 0; mi < 2; mi++) {
        int m0 = wm * 32 + mi * 16 + (lane >> 2);
        #pragma unroll
        for (int ni = 0; ni < 8; ni++) {
            int n = wn * 64 + ni * 8 + (lane & 3) * 2;
            float b0v = bkv[h * 128 + n], b1v = bkv[h * 128 + n + 1];
            #pragma unroll
            for (int rr = 0; rr < 2; rr++) {
                int j = j0 + m0 + rr * 8;
                if (j < HWn) {
                    float v0 = acc[mi][ni][rr * 2] + b0v;
                    float v1 = acc[mi][ni][rr * 2 + 1] + b1v;
                    if (n < 64) {
                        *(uint32_t*)(g_kb + ((size_t)bh * HWn + j) * DKn + n) = bf2(v0, v1);
                    } else {
                        *(float2*)(g_v + ((size_t)bh * HWn + j) * DKn + n - 64) = make_float2(v0, v1);
                    }
                }
            }
        }
    }
}

// ========= Q projection (tf32 mma, 4-stage cp.async, K-phase-split s) ======
// N_TILE=256, M=32, K=512 in 32 slabs of 16 rows (16KB each).
// smem: Ss fp32 [32][256] (32KB, one K-phase) + 4 stages x 16KB = 96KB.
__global__ __launch_bounds__(256) void k_q_m(const float* __restrict__ s,
                                             const float* __restrict__ Wq,
                                             const float* __restrict__ bq) {
    extern __shared__ char sm[];
    const int STG0 = 32768;
    uint32_t base = smem_u32(sm);
    int n0 = blockIdx.x * 256;
    int tid = threadIdx.x, lane = tid & 31, wid = tid >> 5;
    int mrow = lane >> 2, kq = lane & 3;
    auto issue = [&](int slab) {
        uint32_t st = base + STG0 + (slab & 3) * 16384;
        const float* src = Wq + (size_t)(slab * 16) * NQn + n0;
        for (int u = tid; u < 1024; u += 256) {
            int row = u >> 6, g = u & 63;
            cpa16(st + row * 1024 + ((g ^ (row & 7)) << 4),
                  src + (size_t)row * NQn + g * 4);
        }
        CP_COMMIT();
    };
    auto loadSs = [&](int phase) {
        // s[32][256 cols of this phase] -> Ss fp32 swizzled, row stride 1024B
        for (int u = tid; u < 2048; u += 256) {
            int m = u >> 6, g = u & 63;
            float4 v = *(const float4*)(s + (size_t)m * Cn + phase * 256 + g * 4);
            *(float4*)(sm + m * 1024 + ((g ^ (m & 7)) << 4)) = v;
        }
    };
    issue(0); issue(1); issue(2);
    float acc[2][4][4] = {};
    for (int slab = 0; slab < 32; slab++) {
        if (slab + 3 < 32) issue(slab + 3);
        if ((slab & 15) == 0) loadSs(slab >> 4);
        if (slab <= 28) CP_WAIT3();
        else if (slab == 29) CP_WAIT2();
        else if (slab == 30) CP_WAIT1();
        else CP_WAIT0();
        __syncthreads();
        char* st = sm + STG0 + (slab & 3) * 16384;
        int kbase = (slab & 15) * 16;   // k offset within current Ss phase
        #pragma unroll
        for (int ks = 0; ks < 2; ks++) {
            int kb = kbase + ks * 8;
            float af[2][4];
            #pragma unroll
            for (int mi = 0; mi < 2; mi++) {
                int m0 = mi * 16 + mrow;
                int k0 = kb + kq, k1 = kb + 4 + kq;
                int k0g = k0 >> 2, k0o = k0 & 3, k1g = k1 >> 2, k1o = k1 & 3;
                af[mi][0] = *(float*)(sm + m0 * 1024 + ((k0g ^ (m0 & 7)) << 4) + k0o * 4);
                af[mi][1] = *(float*)(sm + (m0 + 8) * 1024 + ((k0g ^ ((m0 + 8) & 7)) << 4) + k0o * 4);
                af[mi][2] = *(float*)(sm + m0 * 1024 + ((k1g ^ (m0 & 7)) << 4) + k1o * 4);
                af[mi][3] = *(float*)(sm + (m0 + 8) * 1024 + ((k1g ^ ((m0 + 8) & 7)) << 4) + k1o * 4);
            }
            int r0 = ks * 8 + kq, r1 = ks * 8 + 4 + kq;
            #pragma unroll
            for (int ni = 0; ni < 4; ni++) {
                int n = wid * 32 + ni * 8 + mrow;
                int g = n >> 2, no = n & 3;
                float b0 = *(float*)(st + r0 * 1024 + ((g ^ (r0 & 7)) << 4) + no * 4);
                float b1 = *(float*)(st + r1 * 1024 + ((g ^ (r1 & 7)) << 4) + no * 4);
                mma_tf32(acc[0][ni], af[0], b0, b1);
                mma_tf32(acc[1][ni], af[1], b0, b1);
            }
        }
        __syncthreads();
    }
    #pragma unroll
    for (int mi = 0; mi < 2; mi++) {
        int m0 = mi * 16 + mrow;
        #pragma unroll
        for (int ni = 0; ni < 4; ni++) {
            int n = n0 + wid * 32 + ni * 8 + kq * 2;
            int i = n >> 9, h = (n >> 6) & 7, d = n & 63;
            float b0v = bq[n], b1v = bq[n + 1];
            #pragma unroll
            for (int rr = 0; rr < 2; rr++) {
                int bidx = m0 + rr * 8;
                *(uint32_t*)(g_qb + (((size_t)bidx * NHn + h) * HWn + i) * DKn + d) =
                    bf2(acc[mi][ni][rr * 2] + b0v, acc[mi][ni][rr * 2 + 1] + b1v);
            }
        }
    }
}

// ================= zero colsum =============================================
__global__ void k_zero() {
    int i = blockIdx.x * blockDim.x + threadIdx.x;
    if (i < BHT * HWn) g_cs[i] = 0.0f;
}

// ======== E = exp(scale*QK^T) (mma) + column sums ==========================
__global__ __launch_bounds__(256) void k_attE_m() {
    __shared__ __nv_bfloat16 Qs[128 * 64];
    __shared__ __nv_bfloat16 Ks[128 * 64];
    int j0 = blockIdx.x * 112, i0 = blockIdx.y * 128, bh = blockIdx.z;
    int tid = threadIdx.x, lane = tid & 31, wid = tid >> 5;
    int wm = wid >> 1, wn = wid & 1;
    uint32_t qBase = smem_u32(Qs), kBase = smem_u32(Ks);
    for (int u = tid; u < 2048; u += 256) {
        int half = u >> 10, w = u & 1023, r = w >> 3, cb = w & 7;
        if (half == 0) {
            int i = min(i0 + r, HWn - 1);
            *(uint4*)((char*)Qs + r * 128 + ((cb ^ (r & 7)) << 4)) =
                *(const uint4*)(g_qb + ((size_t)bh * HWn + i) * DKn + cb * 8);
        } else {
            int j = min(j0 + r, HWn - 1);
            *(uint4*)((char*)Ks + r * 128 + ((cb ^ (r & 7)) << 4)) =
                *(const uint4*)(g_kb + ((size_t)bh * HWn + j) * DKn + cb * 8);
        }
    }
    __syncthreads();
    float acc[2][7][4] = {};
    #pragma unroll
    for (int kk = 0; kk < 4; kk++) {
        uint32_t af[2][4], bf[4][4];
        int cb = kk * 2 + (lane >> 4);
        #pragma unroll
        for (int mi = 0; mi < 2; mi++) {
            int row = wm * 32 + mi * 16 + (lane & 15);
            ldsm4(af[mi], qBase + row * 128 + ((cb ^ (row & 7)) << 4));
        }
        #pragma unroll
        for (int np = 0; np < 4; np++) {
            int row = wn * 56 + np * 16 + (lane & 15);
            ldsm4(bf[np], kBase + row * 128 + ((cb ^ (row & 7)) << 4));
        }
        #pragma unroll
        for (int mi = 0; mi < 2; mi++)
            #pragma unroll
            for (int ni = 0; ni < 7; ni++)
                mma_bf16(acc[mi][ni], af[mi], bf[ni >> 1][ni & 1], bf[ni >> 1][2 + (ni & 1)]);
    }
    #pragma unroll
    for (int ni = 0; ni < 7; ni++) {
        int n = j0 + wn * 56 + ni * 8 + (lane & 3) * 2;
        float cs0 = 0.f, cs1 = 0.f;
        #pragma unroll
        for (int mi = 0; mi < 2; mi++) {
            int ib = i0 + wm * 32 + mi * 16 + (lane >> 2);
            #pragma unroll
            for (int rr = 0; rr < 2; rr++) {
                int i = ib + rr * 8;
                float e0 = 0.f, e1 = 0.f;
                if (i < HWn) {
                    e0 = __expf(acc[mi][ni][rr * 2] * SCALE);
                    e1 = __expf(acc[mi][ni][rr * 2 + 1] * SCALE);
                    *(uint32_t*)(g_Eb + ((size_t)bh * HWn + i) * HWn + n) = bf2(e0, e1);
                }
                cs0 += e0; cs1 += e1;
            }
        }
        #pragma unroll
        for (int o = 4; o <= 16; o <<= 1) {
            cs0 += __shfl_xor_sync(0xffffffffu, cs0, o);
            cs1 += __shfl_xor_sync(0xffffffffu, cs1, o);
        }
        if ((lane >> 2) == 0) {
            atomicAdd(&g_cs[bh * HWn + n], cs0);
            atomicAdd(&g_cs[bh * HWn + n + 1], cs1);
        }
    }
}

// ========== v' = v/colsum, transposed [bh][d][j] bf16 ======================
__global__ __launch_bounds__(256) void k_vnorm_t() {
    __shared__ float t[64][65];
    int j0 = blockIdx.x * 64, bh = blockIdx.y;
    int tid = threadIdx.x;
    for (int u = tid; u < 4096; u += 256) {
        int jj = u >> 6, dd = u & 63;
        t[jj][dd] = g_v[((size_t)bh * HWn + j0 + jj) * DKn + dd] / g_cs[bh * HWn + j0 + jj];
    }
    __syncthreads();
    for (int u = tid; u < 4096; u += 256) {
        int dd = u >> 6, jj = u & 63;
        g_vt[((size_t)bh * DKn + dd) * HWn + j0 + jj] = __float2bfloat16(t[jj][dd]);
    }
}

// ========== AV (mma, cp.async 2-stage): res[i][d] = sum_j E * v' ===========
__global__ __launch_bounds__(256) void k_av_m() {
    extern __shared__ char sm[];
    int i0 = blockIdx.x * 128, bh = blockIdx.y;
    int b = bh >> 3, h = bh & 7;
    int tid = threadIdx.x, lane = tid & 31, wid = tid >> 5;
    int wm = wid >> 1, wn = wid & 1;
    uint32_t base = smem_u32(sm);
    float acc[2][4][4] = {};
    auto issue = [&](int st, int jc) {
        uint32_t eb = base + st * 24576, vb = eb + 16384;
        for (int u = tid; u < 1536; u += 256) {
            if (u < 1024) {
                int r = u >> 3, cb = u & 7;
                int i = min(i0 + r, HWn - 1);
                cpa16(eb + r * 128 + ((cb ^ (r & 7)) << 4),
                      g_Eb + ((size_t)bh * HWn + i) * HWn + jc + cb * 8);
            } else {
                int w = u - 1024, r = w >> 3, cb = w & 7;
                cpa16(vb + r * 128 + ((cb ^ (r & 7)) << 4),
                      g_vt + ((size_t)bh * DKn + r) * HWn + jc + cb * 8);
            }
        }
        CP_COMMIT();
    };
    issue(0, 0);
    for (int s = 0; s < 7; s++) {
        int st = s & 1;
        if (s < 6) { issue(st ^ 1, (s + 1) * 64); CP_WAIT1(); } else { CP_WAIT0(); }
        __syncthreads();
        uint32_t eBase = base + st * 24576, vBase = eBase + 16384;
        #pragma unroll
        for (int kk = 0; kk < 4; kk++) {
            uint32_t af[2][4], bf[2][4];
            int cb = kk * 2 + (lane >> 4);
            #pragma unroll
            for (int mi = 0; mi < 2; mi++) {
                int row = wm * 32 + mi * 16 + (lane & 15);
                ldsm4(af[mi], eBase + row * 128 + ((cb ^ (row & 7)) << 4));
            }
            #pragma unroll
            for (int np = 0; np < 2; np++) {
                int row = wn * 32 + np * 16 + (lane & 15);
                ldsm4(bf[np], vBase + row * 128 + ((cb ^ (row & 7)) << 4));
            }
            #pragma unroll
            for (int mi = 0; mi < 2; mi++)
                #pragma unroll
                for (int ni = 0; ni < 4; ni++)
                    mma_bf16(acc[mi][ni], af[mi], bf[ni >> 1][ni & 1], bf[ni >> 1][2 + (ni & 1)]);
        }
        __syncthreads();
    }
    #pragma unroll
    for (int mi = 0; mi < 2; mi++) {
        int ib = i0 + wm * 32 + mi * 16 + (lane >> 2);
        #pragma unroll
        for (int ni = 0; ni < 4; ni++) {
            int d = wn * 32 + ni * 8 + (lane & 3) * 2;
            #pragma unroll
            for (int rr = 0; rr < 2; rr++) {
                int i = ib + rr * 8;
                if (i < HWn)
                    *(uint32_t*)(g_resb + ((size_t)b * HWn + i) * Cn + h * 64 + d) =
                        bf2(acc[mi][ni][rr * 2], acc[mi][ni][rr * 2 + 1]);
            }
        }
    }
}

// ====== O projection (mma bf16, cp.async 2-stage) + bias + residual ========
__global__ __launch_bounds__(256) void k_out_m(const float* __restrict__ x,
                                               const float* __restrict__ bo,
                                               float* __restrict__ out) {
    extern __shared__ char sm[];
    int b = blockIdx.z, c0 = blockIdx.y * 128, j0 = blockIdx.x * 128;
    int tid = threadIdx.x, lane = tid & 31, wid = tid >> 5;
    int wm = wid >> 1, wn = wid & 1;
    uint32_t base = smem_u32(sm);
    float acc[2][8][4] = {};
    auto issue = [&](int st, int n0) {
        uint32_t ab = base + st * 32768, bb = ab + 16384;
        for (int u = tid; u < 1024; u += 256) {
            int r = u >> 3, cb = u & 7;
            cpa16(ab + r * 128 + ((cb ^ (r & 7)) << 4),
                  g_WoT + (size_t)(c0 + r) * Cn + n0 + cb * 8);
            int j = min(j0 + r, HWn - 1);
            cpa16(bb + r * 128 + ((cb ^ (r & 7)) << 4),
                  g_resb + ((size_t)b * HWn + j) * Cn + n0 + cb * 8);
        }
        CP_COMMIT();
    };
    issue(0, 0);
    for (int s = 0; s < 8; s++) {
        int st = s & 1;
        if (s < 7) { issue(st ^ 1, (s + 1) * 64); CP_WAIT1(); } else { CP_WAIT0(); }
        __syncthreads();
        uint32_t aBase = base + st * 32768, bBase = aBase + 16384;
        #pragma unroll
        for (int kk = 0; kk < 4; kk++) {
            uint32_t af[2][4], bf[4][4];
            int cb = kk * 2 + (lane >> 4);
            #pragma unroll
            for (int mi = 0; mi < 2; mi++) {
                int row = wm * 32 + mi * 16 + (lane & 15);
                ldsm4(af[mi], aBase + row * 128 + ((cb ^ (row & 7)) << 4));
            }
            #pragma unroll
            for (int np = 0; np < 4; np++) {
                int row = wn * 64 + np * 16 + (lane & 15);
                ldsm4(bf[np], bBase + row * 128 + ((cb ^ (row & 7)) << 4));
            }
            #pragma unroll
            for (int mi = 0; mi < 2; mi++)
                #pragma unroll
                for (int ni = 0; ni < 8; ni++)
                    mma_bf16(acc[mi][ni], af[mi], bf[ni >> 1][ni & 1], bf[ni >> 1][2 + (ni & 1)]);
        }
        __syncthreads();
    }
    float* stg = (float*)sm;
    #pragma unroll
    for (int half = 0; half < 2; half++) {
        if (wn == half) {
            #pragma unroll
            for (int mi = 0; mi < 2; mi++) {
                #pragma unroll
                for (int ni = 0; ni < 8; ni++) {
                    int jj = ni * 8 + (lane & 3) * 2;
                    #pragma unroll
                    for (int rr = 0; rr < 2; rr++) {
                        int c = wm * 32 + mi * 16 + (lane >> 2) + rr * 8;
                        stg[c * 66 + jj]     = acc[mi][ni][rr * 2];
                        stg[c * 66 + jj + 1] = acc[mi][ni][rr * 2 + 1];
                    }
                }
            }
        }
        __syncthreads();
        for (int u = tid; u < 4096; u += 256) {
            int c = u >> 5, jj = (u & 31) * 2;
            int j = j0 + half * 64 + jj;
            if (j < HWn) {
                size_t o = ((size_t)b * Cn + c0 + c) * HWn + j;
                float bias = bo[c0 + c];
                float2 xv = *(const float2*)(x + o);
                float2 r = make_float2(stg[c * 66 + jj] + bias + xv.x,
                                       stg[c * 66 + jj + 1] + bias + xv.y);
                *(float2*)(out + o) = r;
            }
        }
        __syncthreads();
    }
}

// ================= launch ==================================================
extern "C" void kernel_launch(void* const* d_in, const int* in_sizes, int n_in,
                              void* d_out, int out_size) {
    const float *x = 0, *s = 0, *Wkv = 0, *bkv = 0, *Wq = 0, *bq = 0, *Wo = 0, *bo = 0;
    for (int i = 0; i < n_in; i++) {
        const float* p = (const float*)d_in[i];
        switch (in_sizes[i]) {
            case 32 * 512 * 448: x = p; break;
            case 32 * 512:       s = p; break;
            case 512 * 1024:     Wkv = p; break;
            case 1024:           bkv = p; break;
            case 512 * 229376:   Wq = p; break;
            case 229376:         bq = p; break;
            case 512 * 512:      Wo = p; break;
            case 512:            bo = p; break;
        }
    }
    float* out = (float*)d_out;

    static int init = 0;
    if (!init) {
        cudaFuncSetAttribute(k_kv_m,  cudaFuncAttributeMaxDynamicSharedMemorySize, 65536);
        cudaFuncSetAttribute(k_q_m,   cudaFuncAttributeMaxDynamicSharedMemorySize, 98304);
        cudaFuncSetAttribute(k_av_m,  cudaFuncAttributeMaxDynamicSharedMemorySize, 49152);
        cudaFuncSetAttribute(k_out_m, cudaFuncAttributeMaxDynamicSharedMemorySize, 65536);
        init = 1;
    }

    k_prep_x <<<dim3(8, 7, Bn), 256>>>(x);
    k_prep_w <<<dim3(8, 16), 256>>>(Wkv);
    k_prep_wo<<<dim3(8, 8), 256>>>(Wo);
    k_q_m    <<<NQn / 256, 256, 98304>>>(s, Wq, bq);
    k_kv_m   <<<dim3(NHn, 4, Bn), 256, 65536>>>(bkv);
    k_zero   <<<(BHT * HWn + 255) / 256, 256>>>();
    k_attE_m <<<dim3(4, 4, BHT), 256>>>();
    k_vnorm_t<<<dim3(7, BHT), 256>>>();
    k_av_m   <<<dim3(4, BHT), 256, 49152>>>();
    k_out_m  <<<dim3(4, 4, Bn), 256, 65536>>>(x, bo, out);
}